// round 8
// baseline (speedup 1.0000x reference)
#include <cuda_runtime.h>
#include <cstdint>

// Embedding gather: out[row, :] = weight[ids[row], :]
// ids: [8192] int32, weight: [32000, 1024] f32, out: [8192, 1024] f32.
//
// R4: L2::evict_last weight reads encoded as 256-bit ld.global.nc.v8.b32
// (ptxas requires v8.b32/v4.b64 with the evict_last modifier on sm_103).
// 256 threads = 2 row-lanes x 128 threads; each thread gathers 32B from
// 4 different rows (4 independent LDG.256 in flight). 8 rows per CTA.

#define DIM        1024
#define ROWS       8
#define THREADS    256
#define LANES      2                 // row-lanes per CTA
#define ROWS_PER_LANE (ROWS / LANES) // 4

struct v8 { uint32_t r[8]; };

__device__ __forceinline__ v8 ldg_evict_last_256(const void* p)
{
    v8 v;
    asm volatile(
        "ld.global.nc.L2::evict_last.v8.b32 {%0,%1,%2,%3,%4,%5,%6,%7}, [%8];"
        : "=r"(v.r[0]), "=r"(v.r[1]), "=r"(v.r[2]), "=r"(v.r[3]),
          "=r"(v.r[4]), "=r"(v.r[5]), "=r"(v.r[6]), "=r"(v.r[7])
        : "l"(p));
    return v;
}

__device__ __forceinline__ void stg_256(void* p, const v8& v)
{
    // two STG.128
    float4* f = reinterpret_cast<float4*>(p);
    f[0] = make_float4(__uint_as_float(v.r[0]), __uint_as_float(v.r[1]),
                       __uint_as_float(v.r[2]), __uint_as_float(v.r[3]));
    f[1] = make_float4(__uint_as_float(v.r[4]), __uint_as_float(v.r[5]),
                       __uint_as_float(v.r[6]), __uint_as_float(v.r[7]));
}

__global__ void __launch_bounds__(THREADS, 8)
embed_gather_kernel(const int* __restrict__ ids,
                    const float* __restrict__ weight,
                    float* __restrict__ out)
{
    const int base = blockIdx.x * ROWS;
    const int t    = threadIdx.x;
    const int lane = t >> 7;          // 0 or 1
    const int col  = (t & 127) * 8;   // float offset within row (32B chunks)

    // 4 ids for this lane: rows base + 2*r + lane, r = 0..3
    int id[ROWS_PER_LANE];
#pragma unroll
    for (int r = 0; r < ROWS_PER_LANE; r++)
        id[r] = __ldg(ids + base + 2 * r + lane);

    // 4 independent 256-bit gathers with L2 retention hint.
    v8 v[ROWS_PER_LANE];
#pragma unroll
    for (int r = 0; r < ROWS_PER_LANE; r++)
        v[r] = ldg_evict_last_256(weight + (size_t)id[r] * DIM + col);

#pragma unroll
    for (int r = 0; r < ROWS_PER_LANE; r++) {
        size_t orow = (size_t)(base + 2 * r + lane) * DIM + col;
        stg_256(out + orow, v[r]);
    }
}

extern "C" void kernel_launch(void* const* d_in, const int* in_sizes, int n_in,
                              void* d_out, int out_size)
{
    const int*   ids    = (const int*)d_in[0];
    const float* weight = (const float*)d_in[1];
    float*       out    = (float*)d_out;

    const int n_rows = in_sizes[0];         // 8192
    const int grid   = n_rows / ROWS;       // 1024

    embed_gather_kernel<<<grid, THREADS>>>(ids, weight, out);
}